// round 12
// baseline (speedup 1.0000x reference)
#include <cuda_runtime.h>
#include <cuda_fp16.h>
#include <cstdint>
#include <math.h>

#define NN 8192
#define DD 256
#define UU 128
#define NITEMS 512    /* 128 ib x 4 jq */

// ================= device scratch (no allocations allowed) =================
__device__ __align__(256) __half         g_xh[NN * UU];    // fp16 split of x (node-major)
__device__ __align__(256) __half         g_xl[NN * UU];
__device__ __align__(256) float          g_x2[NN];
__device__ __align__(256) uint32_t       g_adjb[(size_t)NN * NN / 32]; // permuted adj bits
__device__ __align__(256) float          g_rsump[NN * 4];  // per (i, j-quarter) sums (scaled)
__device__ __align__(256) float          g_mx4[4 * NN * UU]; // j-quarter slices of mx
__device__ int g_ctr;                                       // persistent work counter

// ======================= helpers =======================
__device__ __forceinline__ uint32_t smem_to_u32(const void* p) {
    uint32_t a;
    asm("{ .reg .u64 t; cvta.to.shared.u64 t, %1; cvt.u32.u64 %0, t; }"
        : "=r"(a) : "l"(p));
    return a;
}
__device__ __forceinline__ void cp16(uint32_t saddr, const void* gaddr) {
    asm volatile("cp.async.cg.shared.global [%0], [%1], 16;"
                 :: "r"(saddr), "l"(gaddr));
}
#define CP_COMMIT() asm volatile("cp.async.commit_group;" ::: "memory")
#define CP_WAIT0()  asm volatile("cp.async.wait_group 0;" ::: "memory")

__device__ __forceinline__ void ldsm4(uint32_t& r0, uint32_t& r1, uint32_t& r2,
                                      uint32_t& r3, uint32_t addr) {
    asm volatile("ldmatrix.sync.aligned.m8n8.x4.shared.b16 {%0,%1,%2,%3}, [%4];"
                 : "=r"(r0), "=r"(r1), "=r"(r2), "=r"(r3) : "r"(addr));
}
__device__ __forceinline__ void ldsm4t(uint32_t& r0, uint32_t& r1, uint32_t& r2,
                                       uint32_t& r3, uint32_t addr) {
    asm volatile("ldmatrix.sync.aligned.m8n8.x4.trans.shared.b16 {%0,%1,%2,%3}, [%4];"
                 : "=r"(r0), "=r"(r1), "=r"(r2), "=r"(r3) : "r"(addr));
}
__device__ __forceinline__ void mma_f16(float* d, const uint32_t* a,
                                        uint32_t b0, uint32_t b1) {
    asm volatile("mma.sync.aligned.m16n8k16.row.col.f32.f16.f16.f32 "
                 "{%0,%1,%2,%3}, {%4,%5,%6,%7}, {%8,%9}, {%0,%1,%2,%3};"
                 : "+f"(d[0]), "+f"(d[1]), "+f"(d[2]), "+f"(d[3])
                 : "r"(a[0]), "r"(a[1]), "r"(a[2]), "r"(a[3]), "r"(b0), "r"(b1));
}
__device__ __forceinline__ float fsqrt_fast(float x) {
    float r;
    asm("sqrt.approx.f32 %0, %1;" : "=f"(r) : "f"(x));
    return r;
}
__device__ __forceinline__ uint32_t cvt_f16x2(float hi, float lo) {
    uint32_t r;
    asm("cvt.rn.f16x2.f32 %0, %1, %2;" : "=r"(r) : "f"(hi), "f"(lo));
    return r;
}

__device__ __forceinline__ float blockReduce128(float v, volatile float* sm) {
    #pragma unroll
    for (int o = 16; o > 0; o >>= 1) v += __shfl_xor_sync(0xffffffffu, v, o);
    if ((threadIdx.x & 31) == 0) sm[threadIdx.x >> 5] = v;
    __syncthreads();
    float r = sm[0] + sm[1] + sm[2] + sm[3];
    __syncthreads();
    return r;
}

// w = exp(hyperbolic distance) * 2^-10, closed form; masked by adjacency / dist==0
#define WSC 0.0009765625f
__device__ __forceinline__ float score_w(float xy, float x2i, float x2j, int am) {
    float A = 1.f - 2.f * xy + x2j;
    float B = 1.f - x2i;
    float num = fmaf(A * A, x2i, fmaf(-2.f * A * B, xy, B * B * x2j));
    num = fmaxf(num, 0.f);
    float den = fmaxf(fmaf(x2i, x2j, 1.f - 2.f * xy), 1e-15f);
    float sq  = fsqrt_fast(num);
    float w;
    if (sq < (1.f - 1e-7f) * den) w = __fdividef(den + sq, den - sq) * WSC;
    else                          w = ((2.f - 1e-7f) / 1e-7f) * WSC;
    if (am == 0 || !(sq > 0.f)) w = 0.f;
    return w;
}

// ============================================================
// Stage 1 (k_prep): ALL 8192 blocks build the adjacency bitmask with
// lane-coalesced loads + ballots (permuted bit layout: word = (j/128)*4
// + j%4, bit = (j%128)/4). Blocks < 512 additionally compute
// u = feat@W and x = expmap0(u).
// ============================================================
__global__ __launch_bounds__(256) void k_prep(const float* __restrict__ feat,
                                              const float* __restrict__ W,
                                              const int* __restrict__ adj) {
    __shared__ float fs[16][DD];   // 16 KB
    __shared__ float us[16][UU];   // 8 KB
    int tid = threadIdx.x;
    int wid = tid >> 5, lane = tid & 31;

    // ---- adjacency bitmask: warp handles 1024 consecutive ints ----
    {
        size_t warpg = (size_t)blockIdx.x * 8 + wid;
        const uint4* ap = (const uint4*)adj + warpg * 256;
        uint32_t myword = 0;
        #pragma unroll
        for (int i = 0; i < 8; i++) {
            uint4 v = ap[i * 32 + lane];
            uint32_t b0 = __ballot_sync(0xffffffffu, v.x != 0);
            uint32_t b1 = __ballot_sync(0xffffffffu, v.y != 0);
            uint32_t b2 = __ballot_sync(0xffffffffu, v.z != 0);
            uint32_t b3 = __ballot_sync(0xffffffffu, v.w != 0);
            if ((lane >> 2) == i) {
                int k = lane & 3;
                myword = (k == 0) ? b0 : (k == 1) ? b1 : (k == 2) ? b2 : b3;
            }
        }
        g_adjb[warpg * 32 + lane] = myword;
    }

    if (blockIdx.x >= NN / 16) return;
    int r0 = blockIdx.x * 16;

    // ---- u = feat @ W (16 rows) ----
    for (int idx = tid; idx < 16 * DD; idx += 256)
        fs[idx >> 8][idx & 255] = feat[(size_t)(r0 + (idx >> 8)) * DD + (idx & 255)];
    __syncthreads();

    int col = tid & 127, rg = tid >> 7;
    float acc[8] = {0.f,0.f,0.f,0.f,0.f,0.f,0.f,0.f};
    for (int d = 0; d < DD; d++) {
        float kv = W[d * UU + col];
        #pragma unroll
        for (int r = 0; r < 8; r++)
            acc[r] = fmaf(fs[rg * 8 + r][d], kv, acc[r]);
    }
    #pragma unroll
    for (int r = 0; r < 8; r++)
        us[rg * 8 + r][col] = acc[r];
    __syncthreads();

    // ---- expmap0 per row (row = tid>>4, cols seg*8..seg*8+7) ----
    int row = tid >> 4, seg = tid & 15;
    float v[8], p2 = 0.f;
    #pragma unroll
    for (int q = 0; q < 8; q++) {
        v[q] = us[row][seg * 8 + q];
        p2 = fmaf(v[q], v[q], p2);
    }
    #pragma unroll
    for (int o = 8; o > 0; o >>= 1)
        p2 += __shfl_xor_sync(0xffffffffu, p2, o);
    float n  = fmaxf(sqrtf(p2), 1e-15f);
    float tn = tanhf(n);
    float fac = tn / n;

    __half2 oh[4], ol[4];
    #pragma unroll
    for (int q = 0; q < 4; q++) {
        float x0 = fac * v[2 * q], x1 = fac * v[2 * q + 1];
        __half h0 = __float2half_rn(x0), h1 = __float2half_rn(x1);
        oh[q] = __halves2half2(h0, h1);
        ol[q] = __halves2half2(__float2half_rn(x0 - __half2float(h0)),
                               __float2half_rn(x1 - __half2float(h1)));
    }
    *(uint4*)&g_xh[(size_t)(r0 + row) * UU + seg * 8] = *(uint4*)oh;
    *(uint4*)&g_xl[(size_t)(r0 + row) * UU + seg * 8] = *(uint4*)ol;
    if (seg == 0) g_x2[r0 + row] = tn * tn;
}

// ============================================================
// Stage 2 (k_fused): persistent scores + aggregation, fp16 HMMA.
// grid 304 persistent CTAs pull NITEMS=512 items (128 ib x 4 jq,
// 32 chunks each) from g_ctr. 256 threads; warps 4(m16) x 2(j32).
// GEMM1: 2 products (xh.xh + xh.xl);
// GEMM2: 2 products (wh.xh + wl.xh), B via trans-ldsm on Bh only.
// smem: [A_xh][Bh0][Bl0][Bh1][Bl1] + RS  (87.5 KB -> 2 CTA/SM)
// ============================================================
#define SKA 136
#define AT64 (64 * SKA * 2)            /* 17408 B per 64-row fp16 tile */
#define OS_OFF (1 * AT64)              /* O-reduce staging reuses B tiles */
#define RS_OFF (5 * AT64)
#define G1_SMEM (5 * AT64 + 512)       /* 87552 B */

__device__ __forceinline__ void cp_tile64(char* dst, const __half* src,
                                          int r0, int tid) {
    #pragma unroll
    for (int it = 0; it < 4; it++) {
        int idx = it * 256 + tid;
        int row = idx >> 4, q = idx & 15;
        cp16(smem_to_u32(dst + (row * SKA + q * 8) * 2),
             (const void*)(src + (size_t)(r0 + row) * UU + q * 8));
    }
}

__global__ __launch_bounds__(256, 2) void k_fused() {
    extern __shared__ char smc[];
    __shared__ int s_item;
    uint32_t sb = smem_to_u32(smc);
    int tid = threadIdx.x, wid = tid >> 5, lane = tid & 31;

    int wm = (wid & 3) * 16, wn = (wid >> 2) * 32;
    int g = lane >> 2, tq = lane & 3;
    int aRow = (lane & 7) + ((lane >> 3) & 1) * 8;
    int aCol = (lane >> 4) * 8;
    int bRow = (lane & 7) + (lane >> 4) * 8;
    int bCol = ((lane >> 3) & 1) * 8;
    int tm = lane >> 3, tr = lane & 7;          // trans-ldsm lane mapping
    int k0w = (tq & 1) * 2;                      // adj word pair select

    for (;;) {
        if (tid == 0) s_item = atomicAdd(&g_ctr, 1);
        __syncthreads();
        int item = s_item;
        if (item >= NITEMS) break;
        int ib = item >> 2, jq = item & 3;
        int i0 = ib * 64, jbase = jq * 2048;

        // prologue: A xh resident + B(c=0) hi/lo
        cp_tile64(smc + 0 * AT64, g_xh, i0, tid);
        cp_tile64(smc + 1 * AT64, g_xh, jbase, tid);
        cp_tile64(smc + 2 * AT64, g_xl, jbase, tid);
        CP_COMMIT();

        float x2i[2];
        x2i[0] = g_x2[i0 + wm + g];
        x2i[1] = g_x2[i0 + wm + g + 8];

        float rsum[2] = {0.f, 0.f};
        float o[16][4];
        #pragma unroll
        for (int nb = 0; nb < 16; nb++)
            #pragma unroll
            for (int q = 0; q < 4; q++) o[nb][q] = 0.f;

        CP_WAIT0();
        __syncthreads();

        for (int c = 0; c < 32; c++) {
            int s = c & 1;
            if (c < 31) {   // prefetch next 64-row j-tile into the other stage
                int jn = jbase + (c + 1) * 64;
                cp_tile64(smc + (uint32_t)(1 + 2 * (s ^ 1)) * AT64, g_xh, jn, tid);
                cp_tile64(smc + (uint32_t)(2 + 2 * (s ^ 1)) * AT64, g_xl, jn, tid);
                CP_COMMIT();
            }
            uint32_t Bh = sb + (uint32_t)(1 + 2 * s) * AT64;
            uint32_t Bl = Bh + AT64;

            // ---- GEMM1: xy scores, 2 products (hh + hl) ----
            float acc[4][4];
            #pragma unroll
            for (int nb = 0; nb < 4; nb++)
                #pragma unroll
                for (int q = 0; q < 4; q++) acc[nb][q] = 0.f;

            uint32_t Ah = sb;
            #pragma unroll
            for (int ksv = 0; ksv < 8; ksv++) {
                int k0 = ksv * 16;
                uint32_t ah[4], bh[2][4], bl[2][4];
                ldsm4(ah[0], ah[1], ah[2], ah[3],
                      Ah + (uint32_t)((wm + aRow) * SKA + k0 + aCol) * 2);
                #pragma unroll
                for (int nb = 0; nb < 2; nb++) {
                    ldsm4(bh[nb][0], bh[nb][1], bh[nb][2], bh[nb][3],
                          Bh + (uint32_t)((wn + nb * 16 + bRow) * SKA + k0 + bCol) * 2);
                    ldsm4(bl[nb][0], bl[nb][1], bl[nb][2], bl[nb][3],
                          Bl + (uint32_t)((wn + nb * 16 + bRow) * SKA + k0 + bCol) * 2);
                }
                #pragma unroll
                for (int nb = 0; nb < 2; nb++) {
                    mma_f16(acc[2 * nb],     ah, bh[nb][0], bh[nb][1]);
                    mma_f16(acc[2 * nb + 1], ah, bh[nb][2], bh[nb][3]);
                    mma_f16(acc[2 * nb],     ah, bl[nb][0], bl[nb][1]);
                    mma_f16(acc[2 * nb + 1], ah, bl[nb][2], bl[nb][3]);
                }
            }

            // ---- score epilogue: scaled w -> fp16 hi/lo A fragments ----
            int jc = jbase + c * 64;
            int blk = (jc + wn) >> 7;
            int tb = ((c & 1) << 4) + (wn >> 2) + (tq >> 1);
            float2 x2jv[4];
            #pragma unroll
            for (int nbi = 0; nbi < 4; nbi++)
                x2jv[nbi] = *(const float2*)&g_x2[jc + wn + nbi * 8 + 2 * tq];

            uint32_t wh[2][4], wl[2][4];
            #pragma unroll
            for (int rh = 0; rh < 2; rh++) {
                int ig = i0 + wm + g + rh * 8;
                uint2 mw = *(const uint2*)&g_adjb[(size_t)ig * 256 + blk * 4 + k0w];
                float x2iv = x2i[rh];
                float rs = 0.f;
                #pragma unroll
                for (int nbi = 0; nbi < 4; nbi++) {
                    int tt = tb + 2 * nbi;
                    int a0 = (mw.x >> tt) & 1;
                    int a1 = (mw.y >> tt) & 1;
                    float w0 = score_w(acc[nbi][rh * 2 + 0], x2iv, x2jv[nbi].x, a0);
                    float w1 = score_w(acc[nbi][rh * 2 + 1], x2iv, x2jv[nbi].y, a1);
                    rs += w0 + w1;
                    uint32_t whp = cvt_f16x2(w1, w0);
                    __half2 h2 = *reinterpret_cast<__half2*>(&whp);
                    uint32_t wlp = cvt_f16x2(w1 - __high2float(h2),
                                             w0 - __low2float(h2));
                    int ks = nbi >> 1, ai = (nbi & 1) * 2 + rh;
                    wh[ks][ai] = whp;
                    wl[ks][ai] = wlp;
                }
                rsum[rh] += rs;
            }

            // ---- GEMM2: O += W * Xj (Bh trans-ldsm; wh + wl products) ----
            #pragma unroll
            for (int ks = 0; ks < 2; ks++) {
                #pragma unroll
                for (int np = 0; np < 8; np++) {
                    uint32_t off = (uint32_t)((wn + ks * 16 + (tm & 1) * 8 + tr) * SKA
                                              + np * 16 + (tm >> 1) * 8) * 2;
                    uint32_t bt0, bt1, bt2, bt3;
                    ldsm4t(bt0, bt1, bt2, bt3, Bh + off);
                    mma_f16(o[np * 2],     wh[ks], bt0, bt1);
                    mma_f16(o[np * 2 + 1], wh[ks], bt2, bt3);
                    mma_f16(o[np * 2],     wl[ks], bt0, bt1);
                    mma_f16(o[np * 2 + 1], wl[ks], bt2, bt3);
                }
            }

            if (c < 31) CP_WAIT0();
            __syncthreads();
        }

        // ---- rsum combine + O cross-warp reduction ----
        #pragma unroll
        for (int r = 0; r < 2; r++) {
            rsum[r] += __shfl_xor_sync(0xffffffffu, rsum[r], 1);
            rsum[r] += __shfl_xor_sync(0xffffffffu, rsum[r], 2);
        }
        float* RS = (float*)(smc + RS_OFF);    // [8 warps][16 rows]
        if (tq == 0) {
            RS[wid * 16 + g]     = rsum[0];
            RS[wid * 16 + 8 + g] = rsum[1];
        }
        float* OS = (float*)(smc + OS_OFF);    // 32KB staging (reuses B tiles)
        if (wid >= 4) {
            #pragma unroll
            for (int nb = 0; nb < 16; nb++)
                #pragma unroll
                for (int q = 0; q < 4; q++)
                    OS[(wid - 4) * 2048 + (nb * 4 + q) * 32 + lane] = o[nb][q];
        }
        __syncthreads();

        if (tid < 64) {
            int mt = tid >> 4, idx = tid & 15;
            float v = RS[mt * 16 + idx] + RS[(mt + 4) * 16 + idx];
            g_rsump[(i0 + mt * 16 + idx) * 4 + jq] = v;
        }
        if (wid < 4) {
            #pragma unroll
            for (int nb = 0; nb < 16; nb++) {
                float p0 = OS[wid * 2048 + (nb * 4 + 0) * 32 + lane];
                float p1 = OS[wid * 2048 + (nb * 4 + 1) * 32 + lane];
                float p2 = OS[wid * 2048 + (nb * 4 + 2) * 32 + lane];
                float p3 = OS[wid * 2048 + (nb * 4 + 3) * 32 + lane];
                int irow = i0 + wm + g;
                int dcol = nb * 8 + 2 * tq;
                *(float2*)&g_mx4[((size_t)jq * NN + irow) * UU + dcol] =
                    make_float2(o[nb][0] + p0, o[nb][1] + p1);
                *(float2*)&g_mx4[((size_t)jq * NN + irow + 8) * UU + dcol] =
                    make_float2(o[nb][2] + p2, o[nb][3] + p3);
            }
        }
        __syncthreads();   // OS/RS reads done before next item's loads
    }
}

// ============================================================
// Stage 3: combine quarters, normalize, hyperbolic rescale + mobius bias
// (w-scale 2^-10 cancels in O/rsum)
// ============================================================
__global__ __launch_bounds__(128) void k_epilogue(const float* __restrict__ bias,
                                                  float* __restrict__ out) {
    __shared__ float sm[4];
    int row = blockIdx.x, t = threadIdx.x;

    float rp = (t < 4) ? g_rsump[row * 4 + t] : 0.f;
    float rs = blockReduce128(rp, sm);

    float msum = g_mx4[(size_t)row * UU + t]
               + g_mx4[((size_t)NN + row) * UU + t]
               + g_mx4[((size_t)2 * NN + row) * UU + t]
               + g_mx4[((size_t)3 * NN + row) * UU + t];
    float m = __fdividef(msum, rs);
    float mn2 = blockReduce128(m * m, sm);
    float x2i = g_x2[row];
    float x_n  = fmaxf(sqrtf(x2i), 1e-15f);
    float mx_n = fmaxf(sqrtf(mn2), 1e-15f);
    float xa   = fminf(x_n, 1.f - 1e-7f);
    float art  = 0.5f * (log1pf(xa) - log1pf(-xa));
    float alpha = __fdividef(tanhf(__fdividef(mx_n, x_n) * art), mx_n);
    float ov = alpha * m;

    float bv  = bias[t];
    float bn2 = blockReduce128(bv * bv, sm);
    float bn  = fmaxf(sqrtf(bn2), 1e-15f);
    float bvx = __fdividef(tanhf(bn), bn) * bv;

    float y2  = blockReduce128(bvx * bvx, sm);
    float xy  = blockReduce128(ov * bvx, sm);
    float x2o = blockReduce128(ov * ov, sm);
    float cx  = 1.f + 2.f * xy + y2;
    float cy  = 1.f - x2o;
    float den = fmaxf(fmaf(x2o, y2, 1.f + 2.f * xy), 1e-15f);
    out[(size_t)row * UU + t] = __fdividef(cx * ov + cy * bvx, den);
}

// ============================================================
extern "C" void kernel_launch(void* const* d_in, const int* in_sizes, int n_in,
                              void* d_out, int out_size) {
    const float* feat = (const float*)d_in[0];
    const int*   adj  = (const int*)  d_in[1];
    const float* W    = (const float*)d_in[2];
    const float* bias = (const float*)d_in[3];
    float* out = (float*)d_out;

    cudaFuncSetAttribute(k_fused, cudaFuncAttributeMaxDynamicSharedMemorySize, G1_SMEM);

    void* pctr;
    cudaGetSymbolAddress(&pctr, g_ctr);
    cudaMemsetAsync(pctr, 0, sizeof(int));

    k_prep    <<<NN * NN / 32 / 256, 256>>>(feat, W, adj);
    k_fused   <<<304, 256, G1_SMEM>>>();
    k_epilogue<<<NN, 128>>>(bias, out);
}

// round 13
// speedup vs baseline: 1.0884x; 1.0884x over previous
#include <cuda_runtime.h>
#include <cuda_fp16.h>
#include <cstdint>
#include <math.h>

#define NN 8192
#define DD 256
#define UU 128

// ================= device scratch (no allocations allowed) =================
__device__ __align__(256) __half         g_xh[NN * UU];    // fp16 split of x (node-major)
__device__ __align__(256) __half         g_xl[NN * UU];
__device__ __align__(256) float          g_x2[NN];
__device__ __align__(256) uint32_t       g_adjb[(size_t)NN * NN / 32]; // permuted adj bits
__device__ __align__(256) float          g_rsump[NN * 2];  // per (i, j-half) sums (scaled)
__device__ __align__(256) float          g_mx2[2 * NN * UU]; // j-half slices of mx

// ======================= helpers =======================
__device__ __forceinline__ uint32_t smem_to_u32(const void* p) {
    uint32_t a;
    asm("{ .reg .u64 t; cvta.to.shared.u64 t, %1; cvt.u32.u64 %0, t; }"
        : "=r"(a) : "l"(p));
    return a;
}
__device__ __forceinline__ void cp16(uint32_t saddr, const void* gaddr) {
    asm volatile("cp.async.cg.shared.global [%0], [%1], 16;"
                 :: "r"(saddr), "l"(gaddr));
}
#define CP_COMMIT() asm volatile("cp.async.commit_group;" ::: "memory")
#define CP_WAIT0()  asm volatile("cp.async.wait_group 0;" ::: "memory")

__device__ __forceinline__ void ldsm4(uint32_t& r0, uint32_t& r1, uint32_t& r2,
                                      uint32_t& r3, uint32_t addr) {
    asm volatile("ldmatrix.sync.aligned.m8n8.x4.shared.b16 {%0,%1,%2,%3}, [%4];"
                 : "=r"(r0), "=r"(r1), "=r"(r2), "=r"(r3) : "r"(addr));
}
__device__ __forceinline__ void ldsm4t(uint32_t& r0, uint32_t& r1, uint32_t& r2,
                                       uint32_t& r3, uint32_t addr) {
    asm volatile("ldmatrix.sync.aligned.m8n8.x4.trans.shared.b16 {%0,%1,%2,%3}, [%4];"
                 : "=r"(r0), "=r"(r1), "=r"(r2), "=r"(r3) : "r"(addr));
}
__device__ __forceinline__ void mma_f16(float* d, const uint32_t* a,
                                        uint32_t b0, uint32_t b1) {
    asm volatile("mma.sync.aligned.m16n8k16.row.col.f32.f16.f16.f32 "
                 "{%0,%1,%2,%3}, {%4,%5,%6,%7}, {%8,%9}, {%0,%1,%2,%3};"
                 : "+f"(d[0]), "+f"(d[1]), "+f"(d[2]), "+f"(d[3])
                 : "r"(a[0]), "r"(a[1]), "r"(a[2]), "r"(a[3]), "r"(b0), "r"(b1));
}
__device__ __forceinline__ float fsqrt_fast(float x) {
    float r;
    asm("sqrt.approx.f32 %0, %1;" : "=f"(r) : "f"(x));
    return r;
}
__device__ __forceinline__ uint32_t cvt_f16x2(float hi, float lo) {
    uint32_t r;
    asm("cvt.rn.f16x2.f32 %0, %1, %2;" : "=r"(r) : "f"(hi), "f"(lo));
    return r;
}

__device__ __forceinline__ float blockReduce128(float v, volatile float* sm) {
    #pragma unroll
    for (int o = 16; o > 0; o >>= 1) v += __shfl_xor_sync(0xffffffffu, v, o);
    if ((threadIdx.x & 31) == 0) sm[threadIdx.x >> 5] = v;
    __syncthreads();
    float r = sm[0] + sm[1] + sm[2] + sm[3];
    __syncthreads();
    return r;
}

// w = exp(hyperbolic distance) * 2^-10, closed form; masked by adjacency / dist==0
#define WSC 0.0009765625f
__device__ __forceinline__ float score_w(float xy, float x2i, float x2j, int am) {
    float A = 1.f - 2.f * xy + x2j;
    float B = 1.f - x2i;
    float num = fmaf(A * A, x2i, fmaf(-2.f * A * B, xy, B * B * x2j));
    num = fmaxf(num, 0.f);
    float den = fmaxf(fmaf(x2i, x2j, 1.f - 2.f * xy), 1e-15f);
    float sq  = fsqrt_fast(num);
    float w;
    if (sq < (1.f - 1e-7f) * den) w = __fdividef(den + sq, den - sq) * WSC;
    else                          w = ((2.f - 1e-7f) / 1e-7f) * WSC;
    if (am == 0 || !(sq > 0.f)) w = 0.f;
    return w;
}

// ============================================================
// Stage 1 (k_prep): ALL 8192 blocks build the adjacency bitmask with
// coalesced BATCHED loads (MLP=8) then ballots (permuted layout:
// word = (j/128)*4 + j%4, bit = (j%128)/4). Blocks < 512 additionally
// compute u = feat@W and x = expmap0(u).
// ============================================================
__global__ __launch_bounds__(256) void k_prep(const float* __restrict__ feat,
                                              const float* __restrict__ W,
                                              const int* __restrict__ adj) {
    __shared__ float fs[16][DD];   // 16 KB
    __shared__ float us[16][UU];   // 8 KB
    int tid = threadIdx.x;
    int wid = tid >> 5, lane = tid & 31;

    // ---- adjacency bitmask: warp handles 1024 consecutive ints ----
    {
        size_t warpg = (size_t)blockIdx.x * 8 + wid;
        const uint4* ap = (const uint4*)adj + warpg * 256;
        uint4 v[8];
        #pragma unroll
        for (int i = 0; i < 8; i++) v[i] = ap[i * 32 + lane];   // batched: MLP=8
        uint32_t myword = 0;
        #pragma unroll
        for (int i = 0; i < 8; i++) {
            uint32_t b0 = __ballot_sync(0xffffffffu, v[i].x != 0);
            uint32_t b1 = __ballot_sync(0xffffffffu, v[i].y != 0);
            uint32_t b2 = __ballot_sync(0xffffffffu, v[i].z != 0);
            uint32_t b3 = __ballot_sync(0xffffffffu, v[i].w != 0);
            if ((lane >> 2) == i) {
                int k = lane & 3;
                myword = (k == 0) ? b0 : (k == 1) ? b1 : (k == 2) ? b2 : b3;
            }
        }
        g_adjb[warpg * 32 + lane] = myword;
    }

    if (blockIdx.x >= NN / 16) return;
    int r0 = blockIdx.x * 16;

    // ---- u = feat @ W (16 rows) ----
    for (int idx = tid; idx < 16 * DD; idx += 256)
        fs[idx >> 8][idx & 255] = feat[(size_t)(r0 + (idx >> 8)) * DD + (idx & 255)];
    __syncthreads();

    int col = tid & 127, rg = tid >> 7;
    float acc[8] = {0.f,0.f,0.f,0.f,0.f,0.f,0.f,0.f};
    for (int d = 0; d < DD; d++) {
        float kv = W[d * UU + col];
        #pragma unroll
        for (int r = 0; r < 8; r++)
            acc[r] = fmaf(fs[rg * 8 + r][d], kv, acc[r]);
    }
    #pragma unroll
    for (int r = 0; r < 8; r++)
        us[rg * 8 + r][col] = acc[r];
    __syncthreads();

    // ---- expmap0 per row (row = tid>>4, cols seg*8..seg*8+7) ----
    int row = tid >> 4, seg = tid & 15;
    float v[8], p2 = 0.f;
    #pragma unroll
    for (int q = 0; q < 8; q++) {
        v[q] = us[row][seg * 8 + q];
        p2 = fmaf(v[q], v[q], p2);
    }
    #pragma unroll
    for (int o = 8; o > 0; o >>= 1)
        p2 += __shfl_xor_sync(0xffffffffu, p2, o);
    float n  = fmaxf(sqrtf(p2), 1e-15f);
    float tn = tanhf(n);
    float fac = tn / n;

    __half2 oh[4], ol[4];
    #pragma unroll
    for (int q = 0; q < 4; q++) {
        float x0 = fac * v[2 * q], x1 = fac * v[2 * q + 1];
        __half h0 = __float2half_rn(x0), h1 = __float2half_rn(x1);
        oh[q] = __halves2half2(h0, h1);
        ol[q] = __halves2half2(__float2half_rn(x0 - __half2float(h0)),
                               __float2half_rn(x1 - __half2float(h1)));
    }
    *(uint4*)&g_xh[(size_t)(r0 + row) * UU + seg * 8] = *(uint4*)oh;
    *(uint4*)&g_xl[(size_t)(r0 + row) * UU + seg * 8] = *(uint4*)ol;
    if (seg == 0) g_x2[r0 + row] = tn * tn;
}

// ============================================================
// Stage 2 (k_fused): scores + aggregation, fp16 HMMA.
// grid 256 = 128 ib x 2 jh; 256 threads; warps 4(m16) x 2(j32).
// GEMM1: 2 products (xh.xh + xh.xl);
// GEMM2: 2 products (wh.xh + wl.xh), B via trans-ldsm on Bh only.
// adj bits use the permuted layout from k_prep.
// smem: [A_xh][Bh0][Bl0][Bh1][Bl1] + RS  (87.5 KB -> 2 CTA/SM)
// ============================================================
#define SKA 136
#define AT64 (64 * SKA * 2)            /* 17408 B per 64-row fp16 tile */
#define OS_OFF (1 * AT64)              /* O-reduce staging reuses B tiles */
#define RS_OFF (5 * AT64)
#define G1_SMEM (5 * AT64 + 512)       /* 87552 B */

__device__ __forceinline__ void cp_tile64(char* dst, const __half* src,
                                          int r0, int tid) {
    #pragma unroll
    for (int it = 0; it < 4; it++) {
        int idx = it * 256 + tid;
        int row = idx >> 4, q = idx & 15;
        cp16(smem_to_u32(dst + (row * SKA + q * 8) * 2),
             (const void*)(src + (size_t)(r0 + row) * UU + q * 8));
    }
}

__global__ __launch_bounds__(256, 2) void k_fused() {
    extern __shared__ char smc[];
    uint32_t sb = smem_to_u32(smc);
    int tid = threadIdx.x, wid = tid >> 5, lane = tid & 31;
    int ib = blockIdx.x >> 1, jh = blockIdx.x & 1;
    int i0 = ib * 64, jbase = jh * 4096;

    int wm = (wid & 3) * 16, wn = (wid >> 2) * 32;
    int g = lane >> 2, tq = lane & 3;
    int aRow = (lane & 7) + ((lane >> 3) & 1) * 8;
    int aCol = (lane >> 4) * 8;
    int bRow = (lane & 7) + (lane >> 4) * 8;
    int bCol = ((lane >> 3) & 1) * 8;
    int tm = lane >> 3, tr = lane & 7;          // trans-ldsm lane mapping
    int k0w = (tq & 1) * 2;                      // adj word pair select

    // prologue: A xh resident + B(c=0) hi/lo
    cp_tile64(smc + 0 * AT64, g_xh, i0, tid);
    cp_tile64(smc + 1 * AT64, g_xh, jbase, tid);
    cp_tile64(smc + 2 * AT64, g_xl, jbase, tid);
    CP_COMMIT();

    float x2i[2];
    x2i[0] = g_x2[i0 + wm + g];
    x2i[1] = g_x2[i0 + wm + g + 8];

    float rsum[2] = {0.f, 0.f};
    float o[16][4];
    #pragma unroll
    for (int nb = 0; nb < 16; nb++)
        #pragma unroll
        for (int q = 0; q < 4; q++) o[nb][q] = 0.f;

    CP_WAIT0();
    __syncthreads();

    for (int c = 0; c < 64; c++) {
        int s = c & 1;
        if (c < 63) {   // prefetch next 64-row j-tile into the other stage
            int jn = jbase + (c + 1) * 64;
            cp_tile64(smc + (uint32_t)(1 + 2 * (s ^ 1)) * AT64, g_xh, jn, tid);
            cp_tile64(smc + (uint32_t)(2 + 2 * (s ^ 1)) * AT64, g_xl, jn, tid);
            CP_COMMIT();
        }
        uint32_t Bh = sb + (uint32_t)(1 + 2 * s) * AT64;
        uint32_t Bl = Bh + AT64;

        // ---- GEMM1: xy scores, 2 products (hh + hl) ----
        float acc[4][4];
        #pragma unroll
        for (int nb = 0; nb < 4; nb++)
            #pragma unroll
            for (int q = 0; q < 4; q++) acc[nb][q] = 0.f;

        uint32_t Ah = sb;
        #pragma unroll
        for (int ksv = 0; ksv < 8; ksv++) {
            int k0 = ksv * 16;
            uint32_t ah[4], bh[2][4], bl[2][4];
            ldsm4(ah[0], ah[1], ah[2], ah[3],
                  Ah + (uint32_t)((wm + aRow) * SKA + k0 + aCol) * 2);
            #pragma unroll
            for (int nb = 0; nb < 2; nb++) {
                ldsm4(bh[nb][0], bh[nb][1], bh[nb][2], bh[nb][3],
                      Bh + (uint32_t)((wn + nb * 16 + bRow) * SKA + k0 + bCol) * 2);
                ldsm4(bl[nb][0], bl[nb][1], bl[nb][2], bl[nb][3],
                      Bl + (uint32_t)((wn + nb * 16 + bRow) * SKA + k0 + bCol) * 2);
            }
            #pragma unroll
            for (int nb = 0; nb < 2; nb++) {
                mma_f16(acc[2 * nb],     ah, bh[nb][0], bh[nb][1]);
                mma_f16(acc[2 * nb + 1], ah, bh[nb][2], bh[nb][3]);
                mma_f16(acc[2 * nb],     ah, bl[nb][0], bl[nb][1]);
                mma_f16(acc[2 * nb + 1], ah, bl[nb][2], bl[nb][3]);
            }
        }

        // ---- score epilogue: scaled w -> fp16 hi/lo A fragments ----
        int jc = jbase + c * 64;
        int blk = (jc + wn) >> 7;
        int tb = ((c & 1) << 4) + (wn >> 2) + (tq >> 1);
        float2 x2jv[4];
        #pragma unroll
        for (int nbi = 0; nbi < 4; nbi++)
            x2jv[nbi] = *(const float2*)&g_x2[jc + wn + nbi * 8 + 2 * tq];

        uint32_t wh[2][4], wl[2][4];
        #pragma unroll
        for (int rh = 0; rh < 2; rh++) {
            int ig = i0 + wm + g + rh * 8;
            uint2 mw = *(const uint2*)&g_adjb[(size_t)ig * 256 + blk * 4 + k0w];
            float x2iv = x2i[rh];
            float rs = 0.f;
            #pragma unroll
            for (int nbi = 0; nbi < 4; nbi++) {
                int tt = tb + 2 * nbi;
                int a0 = (mw.x >> tt) & 1;
                int a1 = (mw.y >> tt) & 1;
                float w0 = score_w(acc[nbi][rh * 2 + 0], x2iv, x2jv[nbi].x, a0);
                float w1 = score_w(acc[nbi][rh * 2 + 1], x2iv, x2jv[nbi].y, a1);
                rs += w0 + w1;
                uint32_t whp = cvt_f16x2(w1, w0);
                __half2 h2 = *reinterpret_cast<__half2*>(&whp);
                uint32_t wlp = cvt_f16x2(w1 - __high2float(h2),
                                         w0 - __low2float(h2));
                int ks = nbi >> 1, ai = (nbi & 1) * 2 + rh;
                wh[ks][ai] = whp;
                wl[ks][ai] = wlp;
            }
            rsum[rh] += rs;
        }

        // ---- GEMM2: O += W * Xj  (Bh trans-ldsm only; wh + wl products) ----
        #pragma unroll
        for (int ks = 0; ks < 2; ks++) {
            #pragma unroll
            for (int np = 0; np < 8; np++) {
                uint32_t off = (uint32_t)((wn + ks * 16 + (tm & 1) * 8 + tr) * SKA
                                          + np * 16 + (tm >> 1) * 8) * 2;
                uint32_t bt0, bt1, bt2, bt3;
                ldsm4t(bt0, bt1, bt2, bt3, Bh + off);
                mma_f16(o[np * 2],     wh[ks], bt0, bt1);
                mma_f16(o[np * 2 + 1], wh[ks], bt2, bt3);
                mma_f16(o[np * 2],     wl[ks], bt0, bt1);
                mma_f16(o[np * 2 + 1], wl[ks], bt2, bt3);
            }
        }

        if (c < 63) CP_WAIT0();
        __syncthreads();
    }

    // ---- rsum combine + O cross-warp reduction ----
    #pragma unroll
    for (int r = 0; r < 2; r++) {
        rsum[r] += __shfl_xor_sync(0xffffffffu, rsum[r], 1);
        rsum[r] += __shfl_xor_sync(0xffffffffu, rsum[r], 2);
    }
    float* RS = (float*)(smc + RS_OFF);    // [8 warps][16 rows]
    if (tq == 0) {
        RS[wid * 16 + g]     = rsum[0];
        RS[wid * 16 + 8 + g] = rsum[1];
    }
    float* OS = (float*)(smc + OS_OFF);    // 32KB staging (reuses B tiles)
    if (wid >= 4) {
        #pragma unroll
        for (int nb = 0; nb < 16; nb++)
            #pragma unroll
            for (int q = 0; q < 4; q++)
                OS[(wid - 4) * 2048 + (nb * 4 + q) * 32 + lane] = o[nb][q];
    }
    __syncthreads();

    if (tid < 64) {
        int mt = tid >> 4, idx = tid & 15;
        float v = RS[mt * 16 + idx] + RS[(mt + 4) * 16 + idx];
        g_rsump[(i0 + mt * 16 + idx) * 2 + jh] = v;
    }
    if (wid < 4) {
        #pragma unroll
        for (int nb = 0; nb < 16; nb++) {
            float p0 = OS[wid * 2048 + (nb * 4 + 0) * 32 + lane];
            float p1 = OS[wid * 2048 + (nb * 4 + 1) * 32 + lane];
            float p2 = OS[wid * 2048 + (nb * 4 + 2) * 32 + lane];
            float p3 = OS[wid * 2048 + (nb * 4 + 3) * 32 + lane];
            int irow = i0 + wm + g;
            int dcol = nb * 8 + 2 * tq;
            *(float2*)&g_mx2[((size_t)jh * NN + irow) * UU + dcol] =
                make_float2(o[nb][0] + p0, o[nb][1] + p1);
            *(float2*)&g_mx2[((size_t)jh * NN + irow + 8) * UU + dcol] =
                make_float2(o[nb][2] + p2, o[nb][3] + p3);
        }
    }
}

// ============================================================
// Stage 3: combine halves, normalize, hyperbolic rescale + mobius bias
// (w-scale 2^-10 cancels in O/rsum)
// ============================================================
__global__ __launch_bounds__(128) void k_epilogue(const float* __restrict__ bias,
                                                  float* __restrict__ out) {
    __shared__ float sm[4];
    int row = blockIdx.x, t = threadIdx.x;

    float rp = (t < 2) ? g_rsump[row * 2 + t] : 0.f;
    float rs = blockReduce128(rp, sm);

    float m = __fdividef(g_mx2[(size_t)row * UU + t] +
                         g_mx2[(size_t)(NN + row) * UU + t], rs);
    float mn2 = blockReduce128(m * m, sm);
    float x2i = g_x2[row];
    float x_n  = fmaxf(sqrtf(x2i), 1e-15f);
    float mx_n = fmaxf(sqrtf(mn2), 1e-15f);
    float xa   = fminf(x_n, 1.f - 1e-7f);
    float art  = 0.5f * (log1pf(xa) - log1pf(-xa));
    float alpha = __fdividef(tanhf(__fdividef(mx_n, x_n) * art), mx_n);
    float ov = alpha * m;

    float bv  = bias[t];
    float bn2 = blockReduce128(bv * bv, sm);
    float bn  = fmaxf(sqrtf(bn2), 1e-15f);
    float bvx = __fdividef(tanhf(bn), bn) * bv;

    float y2  = blockReduce128(bvx * bvx, sm);
    float xy  = blockReduce128(ov * bvx, sm);
    float x2o = blockReduce128(ov * ov, sm);
    float cx  = 1.f + 2.f * xy + y2;
    float cy  = 1.f - x2o;
    float den = fmaxf(fmaf(x2o, y2, 1.f + 2.f * xy), 1e-15f);
    out[(size_t)row * UU + t] = __fdividef(cx * ov + cy * bvx, den);
}

// ============================================================
extern "C" void kernel_launch(void* const* d_in, const int* in_sizes, int n_in,
                              void* d_out, int out_size) {
    const float* feat = (const float*)d_in[0];
    const int*   adj  = (const int*)  d_in[1];
    const float* W    = (const float*)d_in[2];
    const float* bias = (const float*)d_in[3];
    float* out = (float*)d_out;

    cudaFuncSetAttribute(k_fused, cudaFuncAttributeMaxDynamicSharedMemorySize, G1_SMEM);

    k_prep    <<<NN * NN / 32 / 256, 256>>>(feat, W, adj);
    k_fused   <<<256, 256, G1_SMEM>>>();
    k_epilogue<<<NN, 128>>>(bias, out);
}

// round 14
// speedup vs baseline: 1.1656x; 1.0709x over previous
#include <cuda_runtime.h>
#include <cuda_fp16.h>
#include <cstdint>
#include <math.h>

#define NN 8192
#define DD 256
#define UU 128

// ================= device scratch (no allocations allowed) =================
__device__ __align__(256) __half         g_xh[NN * UU];    // fp16 split of x (node-major)
__device__ __align__(256) __half         g_xl[NN * UU];
__device__ __align__(256) float          g_x2[NN];
__device__ __align__(256) uint32_t       g_adjb[(size_t)NN * NN / 32]; // permuted adj bits
__device__ __align__(256) float          g_rsump[NN * 2];  // per (i, j-half) sums (scaled)
__device__ __align__(256) float          g_mx2[2 * NN * UU]; // j-half slices of mx

// ======================= helpers =======================
__device__ __forceinline__ uint32_t smem_to_u32(const void* p) {
    uint32_t a;
    asm("{ .reg .u64 t; cvta.to.shared.u64 t, %1; cvt.u32.u64 %0, t; }"
        : "=r"(a) : "l"(p));
    return a;
}
__device__ __forceinline__ void cp16(uint32_t saddr, const void* gaddr) {
    asm volatile("cp.async.cg.shared.global [%0], [%1], 16;"
                 :: "r"(saddr), "l"(gaddr));
}
#define CP_COMMIT() asm volatile("cp.async.commit_group;" ::: "memory")
#define CP_WAIT0()  asm volatile("cp.async.wait_group 0;" ::: "memory")

__device__ __forceinline__ void ldsm4(uint32_t& r0, uint32_t& r1, uint32_t& r2,
                                      uint32_t& r3, uint32_t addr) {
    asm volatile("ldmatrix.sync.aligned.m8n8.x4.shared.b16 {%0,%1,%2,%3}, [%4];"
                 : "=r"(r0), "=r"(r1), "=r"(r2), "=r"(r3) : "r"(addr));
}
__device__ __forceinline__ void ldsm4t(uint32_t& r0, uint32_t& r1, uint32_t& r2,
                                       uint32_t& r3, uint32_t addr) {
    asm volatile("ldmatrix.sync.aligned.m8n8.x4.trans.shared.b16 {%0,%1,%2,%3}, [%4];"
                 : "=r"(r0), "=r"(r1), "=r"(r2), "=r"(r3) : "r"(addr));
}
__device__ __forceinline__ void mma_f16(float* d, const uint32_t* a,
                                        uint32_t b0, uint32_t b1) {
    asm volatile("mma.sync.aligned.m16n8k16.row.col.f32.f16.f16.f32 "
                 "{%0,%1,%2,%3}, {%4,%5,%6,%7}, {%8,%9}, {%0,%1,%2,%3};"
                 : "+f"(d[0]), "+f"(d[1]), "+f"(d[2]), "+f"(d[3])
                 : "r"(a[0]), "r"(a[1]), "r"(a[2]), "r"(a[3]), "r"(b0), "r"(b1));
}
__device__ __forceinline__ float fsqrt_fast(float x) {
    float r;
    asm("sqrt.approx.f32 %0, %1;" : "=f"(r) : "f"(x));
    return r;
}
__device__ __forceinline__ uint32_t cvt_f16x2(float hi, float lo) {
    uint32_t r;
    asm("cvt.rn.f16x2.f32 %0, %1, %2;" : "=r"(r) : "f"(hi), "f"(lo));
    return r;
}

__device__ __forceinline__ float blockReduce128(float v, volatile float* sm) {
    #pragma unroll
    for (int o = 16; o > 0; o >>= 1) v += __shfl_xor_sync(0xffffffffu, v, o);
    if ((threadIdx.x & 31) == 0) sm[threadIdx.x >> 5] = v;
    __syncthreads();
    float r = sm[0] + sm[1] + sm[2] + sm[3];
    __syncthreads();
    return r;
}

// w = exp(hyperbolic distance) * 2^-10, closed form; masked by adjacency / dist==0
#define WSC 0.0009765625f
__device__ __forceinline__ float score_w(float xy, float x2i, float x2j, int am) {
    float A = 1.f - 2.f * xy + x2j;
    float B = 1.f - x2i;
    float num = fmaf(A * A, x2i, fmaf(-2.f * A * B, xy, B * B * x2j));
    num = fmaxf(num, 0.f);
    float den = fmaxf(fmaf(x2i, x2j, 1.f - 2.f * xy), 1e-15f);
    float sq  = fsqrt_fast(num);
    float w;
    if (sq < (1.f - 1e-7f) * den) w = __fdividef(den + sq, den - sq) * WSC;
    else                          w = ((2.f - 1e-7f) / 1e-7f) * WSC;
    if (am == 0 || !(sq > 0.f)) w = 0.f;
    return w;
}

// ============================================================
// Stage 1 (k_prep): ALL 8192 blocks build the adjacency bitmask with
// coalesced BATCHED loads (MLP=8) then ballots (permuted layout:
// word = (j/128)*4 + j%4, bit = (j%128)/4). Blocks < 512 additionally
// compute u = feat@W and x = expmap0(u).
// ============================================================
__global__ __launch_bounds__(256) void k_prep(const float* __restrict__ feat,
                                              const float* __restrict__ W,
                                              const int* __restrict__ adj) {
    __shared__ float fs[16][DD];   // 16 KB
    __shared__ float us[16][UU];   // 8 KB
    int tid = threadIdx.x;
    int wid = tid >> 5, lane = tid & 31;

    // ---- adjacency bitmask: warp handles 1024 consecutive ints ----
    {
        size_t warpg = (size_t)blockIdx.x * 8 + wid;
        const uint4* ap = (const uint4*)adj + warpg * 256;
        uint4 v[8];
        #pragma unroll
        for (int i = 0; i < 8; i++) v[i] = ap[i * 32 + lane];   // batched: MLP=8
        uint32_t myword = 0;
        #pragma unroll
        for (int i = 0; i < 8; i++) {
            uint32_t b0 = __ballot_sync(0xffffffffu, v[i].x != 0);
            uint32_t b1 = __ballot_sync(0xffffffffu, v[i].y != 0);
            uint32_t b2 = __ballot_sync(0xffffffffu, v[i].z != 0);
            uint32_t b3 = __ballot_sync(0xffffffffu, v[i].w != 0);
            if ((lane >> 2) == i) {
                int k = lane & 3;
                myword = (k == 0) ? b0 : (k == 1) ? b1 : (k == 2) ? b2 : b3;
            }
        }
        g_adjb[warpg * 32 + lane] = myword;
    }

    if (blockIdx.x >= NN / 16) return;
    int r0 = blockIdx.x * 16;

    // ---- u = feat @ W (16 rows) ----
    for (int idx = tid; idx < 16 * DD; idx += 256)
        fs[idx >> 8][idx & 255] = feat[(size_t)(r0 + (idx >> 8)) * DD + (idx & 255)];
    __syncthreads();

    int col = tid & 127, rg = tid >> 7;
    float acc[8] = {0.f,0.f,0.f,0.f,0.f,0.f,0.f,0.f};
    for (int d = 0; d < DD; d++) {
        float kv = W[d * UU + col];
        #pragma unroll
        for (int r = 0; r < 8; r++)
            acc[r] = fmaf(fs[rg * 8 + r][d], kv, acc[r]);
    }
    #pragma unroll
    for (int r = 0; r < 8; r++)
        us[rg * 8 + r][col] = acc[r];
    __syncthreads();

    // ---- expmap0 per row (row = tid>>4, cols seg*8..seg*8+7) ----
    int row = tid >> 4, seg = tid & 15;
    float v[8], p2 = 0.f;
    #pragma unroll
    for (int q = 0; q < 8; q++) {
        v[q] = us[row][seg * 8 + q];
        p2 = fmaf(v[q], v[q], p2);
    }
    #pragma unroll
    for (int o = 8; o > 0; o >>= 1)
        p2 += __shfl_xor_sync(0xffffffffu, p2, o);
    float n  = fmaxf(sqrtf(p2), 1e-15f);
    float tn = tanhf(n);
    float fac = tn / n;

    __half2 oh[4], ol[4];
    #pragma unroll
    for (int q = 0; q < 4; q++) {
        float x0 = fac * v[2 * q], x1 = fac * v[2 * q + 1];
        __half h0 = __float2half_rn(x0), h1 = __float2half_rn(x1);
        oh[q] = __halves2half2(h0, h1);
        ol[q] = __halves2half2(__float2half_rn(x0 - __half2float(h0)),
                               __float2half_rn(x1 - __half2float(h1)));
    }
    *(uint4*)&g_xh[(size_t)(r0 + row) * UU + seg * 8] = *(uint4*)oh;
    *(uint4*)&g_xl[(size_t)(r0 + row) * UU + seg * 8] = *(uint4*)ol;
    if (seg == 0) g_x2[r0 + row] = tn * tn;
}

// ============================================================
// Stage 2 (k_fused): scores + aggregation, fp16 HMMA.
// grid 256 = 128 ib x 2 jh; 256 threads; warps 4(m16) x 2(j32).
// GEMM1: 2 products (xh_i.xh_j + xl_i.xh_j) -- Al RESIDENT, no Bl tile;
// GEMM2: 2 products (wh.xh + wl.xh), B via trans-ldsm on Bh only.
// Per chunk only ONE Bh tile streams through smem (halved STS/cp.async).
// smem: [Ah][Al][Bh0][Bh1] + RS  (68.5 KB -> 2 CTA/SM)
// ============================================================
#define SKA 136
#define AT64 (64 * SKA * 2)            /* 17408 B per 64-row fp16 tile */
#define OS_OFF (2 * AT64)              /* O-reduce staging reuses Bh tiles */
#define RS_OFF (4 * AT64)
#define G1_SMEM (4 * AT64 + 512)       /* 70144 B */

__device__ __forceinline__ void cp_tile64(char* dst, const __half* src,
                                          int r0, int tid) {
    #pragma unroll
    for (int it = 0; it < 4; it++) {
        int idx = it * 256 + tid;
        int row = idx >> 4, q = idx & 15;
        cp16(smem_to_u32(dst + (row * SKA + q * 8) * 2),
             (const void*)(src + (size_t)(r0 + row) * UU + q * 8));
    }
}

__global__ __launch_bounds__(256, 2) void k_fused() {
    extern __shared__ char smc[];
    uint32_t sb = smem_to_u32(smc);
    int tid = threadIdx.x, wid = tid >> 5, lane = tid & 31;
    int ib = blockIdx.x >> 1, jh = blockIdx.x & 1;
    int i0 = ib * 64, jbase = jh * 4096;

    int wm = (wid & 3) * 16, wn = (wid >> 2) * 32;
    int g = lane >> 2, tq = lane & 3;
    int aRow = (lane & 7) + ((lane >> 3) & 1) * 8;
    int aCol = (lane >> 4) * 8;
    int bRow = (lane & 7) + (lane >> 4) * 8;
    int bCol = ((lane >> 3) & 1) * 8;
    int tm = lane >> 3, tr = lane & 7;          // trans-ldsm lane mapping
    int k0w = (tq & 1) * 2;                      // adj word pair select

    // prologue: Ah + Al resident + Bh(c=0)
    cp_tile64(smc + 0 * AT64, g_xh, i0, tid);
    cp_tile64(smc + 1 * AT64, g_xl, i0, tid);
    cp_tile64(smc + 2 * AT64, g_xh, jbase, tid);
    CP_COMMIT();

    float x2i[2];
    x2i[0] = g_x2[i0 + wm + g];
    x2i[1] = g_x2[i0 + wm + g + 8];

    float rsum[2] = {0.f, 0.f};
    float o[16][4];
    #pragma unroll
    for (int nb = 0; nb < 16; nb++)
        #pragma unroll
        for (int q = 0; q < 4; q++) o[nb][q] = 0.f;

    CP_WAIT0();
    __syncthreads();

    for (int c = 0; c < 64; c++) {
        int s = c & 1;
        if (c < 63) {   // prefetch next 64-row Bh tile into the other stage
            int jn = jbase + (c + 1) * 64;
            cp_tile64(smc + (uint32_t)(2 + (s ^ 1)) * AT64, g_xh, jn, tid);
            CP_COMMIT();
        }
        uint32_t Bh = sb + (uint32_t)(2 + s) * AT64;

        // ---- GEMM1: xy scores, 2 products (hh + lh), A-lo resident ----
        float acc[4][4];
        #pragma unroll
        for (int nb = 0; nb < 4; nb++)
            #pragma unroll
            for (int q = 0; q < 4; q++) acc[nb][q] = 0.f;

        uint32_t Ah = sb, Al = sb + AT64;
        #pragma unroll
        for (int ksv = 0; ksv < 8; ksv++) {
            int k0 = ksv * 16;
            uint32_t ah[4], al[4], bh[2][4];
            ldsm4(ah[0], ah[1], ah[2], ah[3],
                  Ah + (uint32_t)((wm + aRow) * SKA + k0 + aCol) * 2);
            ldsm4(al[0], al[1], al[2], al[3],
                  Al + (uint32_t)((wm + aRow) * SKA + k0 + aCol) * 2);
            #pragma unroll
            for (int nb = 0; nb < 2; nb++)
                ldsm4(bh[nb][0], bh[nb][1], bh[nb][2], bh[nb][3],
                      Bh + (uint32_t)((wn + nb * 16 + bRow) * SKA + k0 + bCol) * 2);
            #pragma unroll
            for (int nb = 0; nb < 2; nb++) {
                mma_f16(acc[2 * nb],     ah, bh[nb][0], bh[nb][1]);
                mma_f16(acc[2 * nb + 1], ah, bh[nb][2], bh[nb][3]);
                mma_f16(acc[2 * nb],     al, bh[nb][0], bh[nb][1]);
                mma_f16(acc[2 * nb + 1], al, bh[nb][2], bh[nb][3]);
            }
        }

        // ---- score epilogue: scaled w -> fp16 hi/lo A fragments ----
        int jc = jbase + c * 64;
        int blk = (jc + wn) >> 7;
        int tb = ((c & 1) << 4) + (wn >> 2) + (tq >> 1);
        float2 x2jv[4];
        #pragma unroll
        for (int nbi = 0; nbi < 4; nbi++)
            x2jv[nbi] = *(const float2*)&g_x2[jc + wn + nbi * 8 + 2 * tq];

        uint32_t wh[2][4], wl[2][4];
        #pragma unroll
        for (int rh = 0; rh < 2; rh++) {
            int ig = i0 + wm + g + rh * 8;
            uint2 mw = *(const uint2*)&g_adjb[(size_t)ig * 256 + blk * 4 + k0w];
            float x2iv = x2i[rh];
            float rs = 0.f;
            #pragma unroll
            for (int nbi = 0; nbi < 4; nbi++) {
                int tt = tb + 2 * nbi;
                int a0 = (mw.x >> tt) & 1;
                int a1 = (mw.y >> tt) & 1;
                float w0 = score_w(acc[nbi][rh * 2 + 0], x2iv, x2jv[nbi].x, a0);
                float w1 = score_w(acc[nbi][rh * 2 + 1], x2iv, x2jv[nbi].y, a1);
                rs += w0 + w1;
                uint32_t whp = cvt_f16x2(w1, w0);
                __half2 h2 = *reinterpret_cast<__half2*>(&whp);
                uint32_t wlp = cvt_f16x2(w1 - __high2float(h2),
                                         w0 - __low2float(h2));
                int ks = nbi >> 1, ai = (nbi & 1) * 2 + rh;
                wh[ks][ai] = whp;
                wl[ks][ai] = wlp;
            }
            rsum[rh] += rs;
        }

        // ---- GEMM2: O += W * Xj  (Bh trans-ldsm only; wh + wl products) ----
        #pragma unroll
        for (int ks = 0; ks < 2; ks++) {
            #pragma unroll
            for (int np = 0; np < 8; np++) {
                uint32_t off = (uint32_t)((wn + ks * 16 + (tm & 1) * 8 + tr) * SKA
                                          + np * 16 + (tm >> 1) * 8) * 2;
                uint32_t bt0, bt1, bt2, bt3;
                ldsm4t(bt0, bt1, bt2, bt3, Bh + off);
                mma_f16(o[np * 2],     wh[ks], bt0, bt1);
                mma_f16(o[np * 2 + 1], wh[ks], bt2, bt3);
                mma_f16(o[np * 2],     wl[ks], bt0, bt1);
                mma_f16(o[np * 2 + 1], wl[ks], bt2, bt3);
            }
        }

        if (c < 63) CP_WAIT0();
        __syncthreads();
    }

    // ---- rsum combine + O cross-warp reduction ----
    #pragma unroll
    for (int r = 0; r < 2; r++) {
        rsum[r] += __shfl_xor_sync(0xffffffffu, rsum[r], 1);
        rsum[r] += __shfl_xor_sync(0xffffffffu, rsum[r], 2);
    }
    float* RS = (float*)(smc + RS_OFF);    // [8 warps][16 rows]
    if (tq == 0) {
        RS[wid * 16 + g]     = rsum[0];
        RS[wid * 16 + 8 + g] = rsum[1];
    }
    float* OS = (float*)(smc + OS_OFF);    // 32KB staging (reuses Bh tiles)
    if (wid >= 4) {
        #pragma unroll
        for (int nb = 0; nb < 16; nb++)
            #pragma unroll
            for (int q = 0; q < 4; q++)
                OS[(wid - 4) * 2048 + (nb * 4 + q) * 32 + lane] = o[nb][q];
    }
    __syncthreads();

    if (tid < 64) {
        int mt = tid >> 4, idx = tid & 15;
        float v = RS[mt * 16 + idx] + RS[(mt + 4) * 16 + idx];
        g_rsump[(i0 + mt * 16 + idx) * 2 + jh] = v;
    }
    if (wid < 4) {
        #pragma unroll
        for (int nb = 0; nb < 16; nb++) {
            float p0 = OS[wid * 2048 + (nb * 4 + 0) * 32 + lane];
            float p1 = OS[wid * 2048 + (nb * 4 + 1) * 32 + lane];
            float p2 = OS[wid * 2048 + (nb * 4 + 2) * 32 + lane];
            float p3 = OS[wid * 2048 + (nb * 4 + 3) * 32 + lane];
            int irow = i0 + wm + g;
            int dcol = nb * 8 + 2 * tq;
            *(float2*)&g_mx2[((size_t)jh * NN + irow) * UU + dcol] =
                make_float2(o[nb][0] + p0, o[nb][1] + p1);
            *(float2*)&g_mx2[((size_t)jh * NN + irow + 8) * UU + dcol] =
                make_float2(o[nb][2] + p2, o[nb][3] + p3);
        }
    }
}

// ============================================================
// Stage 3: combine halves, normalize, hyperbolic rescale + mobius bias
// (w-scale 2^-10 cancels in O/rsum)
// ============================================================
__global__ __launch_bounds__(128) void k_epilogue(const float* __restrict__ bias,
                                                  float* __restrict__ out) {
    __shared__ float sm[4];
    int row = blockIdx.x, t = threadIdx.x;

    float rp = (t < 2) ? g_rsump[row * 2 + t] : 0.f;
    float rs = blockReduce128(rp, sm);

    float m = __fdividef(g_mx2[(size_t)row * UU + t] +
                         g_mx2[(size_t)(NN + row) * UU + t], rs);
    float mn2 = blockReduce128(m * m, sm);
    float x2i = g_x2[row];
    float x_n  = fmaxf(sqrtf(x2i), 1e-15f);
    float mx_n = fmaxf(sqrtf(mn2), 1e-15f);
    float xa   = fminf(x_n, 1.f - 1e-7f);
    float art  = 0.5f * (log1pf(xa) - log1pf(-xa));
    float alpha = __fdividef(tanhf(__fdividef(mx_n, x_n) * art), mx_n);
    float ov = alpha * m;

    float bv  = bias[t];
    float bn2 = blockReduce128(bv * bv, sm);
    float bn  = fmaxf(sqrtf(bn2), 1e-15f);
    float bvx = __fdividef(tanhf(bn), bn) * bv;

    float y2  = blockReduce128(bvx * bvx, sm);
    float xy  = blockReduce128(ov * bvx, sm);
    float x2o = blockReduce128(ov * ov, sm);
    float cx  = 1.f + 2.f * xy + y2;
    float cy  = 1.f - x2o;
    float den = fmaxf(fmaf(x2o, y2, 1.f + 2.f * xy), 1e-15f);
    out[(size_t)row * UU + t] = __fdividef(cx * ov + cy * bvx, den);
}

// ============================================================
extern "C" void kernel_launch(void* const* d_in, const int* in_sizes, int n_in,
                              void* d_out, int out_size) {
    const float* feat = (const float*)d_in[0];
    const int*   adj  = (const int*)  d_in[1];
    const float* W    = (const float*)d_in[2];
    const float* bias = (const float*)d_in[3];
    float* out = (float*)d_out;

    cudaFuncSetAttribute(k_fused, cudaFuncAttributeMaxDynamicSharedMemorySize, G1_SMEM);

    k_prep    <<<NN * NN / 32 / 256, 256>>>(feat, W, adj);
    k_fused   <<<256, 256, G1_SMEM>>>();
    k_epilogue<<<NN, 128>>>(bias, out);
}

// round 15
// speedup vs baseline: 1.3227x; 1.1348x over previous
#include <cuda_runtime.h>
#include <cuda_fp16.h>
#include <cstdint>
#include <math.h>

#define NN 8192
#define DD 256
#define UU 128

// ================= device scratch (no allocations allowed) =================
__device__ __align__(256) __half         g_xh[NN * UU];    // fp16 split of x (node-major)
__device__ __align__(256) __half         g_xl[NN * UU];
__device__ __align__(256) float          g_x2[NN];
__device__ __align__(256) uint32_t       g_adjb[(size_t)NN * NN / 32]; // permuted adj bits
__device__ __align__(256) float          g_rsump[NN * 2];  // per (i, j-half) sums (scaled)
__device__ __align__(256) float          g_mx2[2 * NN * UU]; // j-half slices of mx

// ======================= helpers =======================
__device__ __forceinline__ uint32_t smem_to_u32(const void* p) {
    uint32_t a;
    asm("{ .reg .u64 t; cvta.to.shared.u64 t, %1; cvt.u32.u64 %0, t; }"
        : "=r"(a) : "l"(p));
    return a;
}
__device__ __forceinline__ void cp16(uint32_t saddr, const void* gaddr) {
    asm volatile("cp.async.cg.shared.global [%0], [%1], 16;"
                 :: "r"(saddr), "l"(gaddr));
}
#define CP_COMMIT() asm volatile("cp.async.commit_group;" ::: "memory")
#define CP_WAIT0()  asm volatile("cp.async.wait_group 0;" ::: "memory")

__device__ __forceinline__ void ldsm4(uint32_t& r0, uint32_t& r1, uint32_t& r2,
                                      uint32_t& r3, uint32_t addr) {
    asm volatile("ldmatrix.sync.aligned.m8n8.x4.shared.b16 {%0,%1,%2,%3}, [%4];"
                 : "=r"(r0), "=r"(r1), "=r"(r2), "=r"(r3) : "r"(addr));
}
__device__ __forceinline__ void ldsm4t(uint32_t& r0, uint32_t& r1, uint32_t& r2,
                                       uint32_t& r3, uint32_t addr) {
    asm volatile("ldmatrix.sync.aligned.m8n8.x4.trans.shared.b16 {%0,%1,%2,%3}, [%4];"
                 : "=r"(r0), "=r"(r1), "=r"(r2), "=r"(r3) : "r"(addr));
}
__device__ __forceinline__ void mma_f16(float* d, const uint32_t* a,
                                        uint32_t b0, uint32_t b1) {
    asm volatile("mma.sync.aligned.m16n8k16.row.col.f32.f16.f16.f32 "
                 "{%0,%1,%2,%3}, {%4,%5,%6,%7}, {%8,%9}, {%0,%1,%2,%3};"
                 : "+f"(d[0]), "+f"(d[1]), "+f"(d[2]), "+f"(d[3])
                 : "r"(a[0]), "r"(a[1]), "r"(a[2]), "r"(a[3]), "r"(b0), "r"(b1));
}
__device__ __forceinline__ float fsqrt_fast(float x) {
    float r;
    asm("sqrt.approx.f32 %0, %1;" : "=f"(r) : "f"(x));
    return r;
}
__device__ __forceinline__ uint32_t cvt_f16x2(float hi, float lo) {
    uint32_t r;
    asm("cvt.rn.f16x2.f32 %0, %1, %2;" : "=r"(r) : "f"(hi), "f"(lo));
    return r;
}

__device__ __forceinline__ float blockReduce128(float v, volatile float* sm) {
    #pragma unroll
    for (int o = 16; o > 0; o >>= 1) v += __shfl_xor_sync(0xffffffffu, v, o);
    if ((threadIdx.x & 31) == 0) sm[threadIdx.x >> 5] = v;
    __syncthreads();
    float r = sm[0] + sm[1] + sm[2] + sm[3];
    __syncthreads();
    return r;
}

// w = exp(hyperbolic distance) * 2^-10, closed form; masked by adjacency / dist==0
#define WSC 0.0009765625f
__device__ __forceinline__ float score_w(float xy, float x2i, float x2j, int am) {
    float A = 1.f - 2.f * xy + x2j;
    float B = 1.f - x2i;
    float num = fmaf(A * A, x2i, fmaf(-2.f * A * B, xy, B * B * x2j));
    num = fmaxf(num, 0.f);
    float den = fmaxf(fmaf(x2i, x2j, 1.f - 2.f * xy), 1e-15f);
    float sq  = fsqrt_fast(num);
    float w;
    if (sq < (1.f - 1e-7f) * den) w = __fdividef(den + sq, den - sq) * WSC;
    else                          w = ((2.f - 1e-7f) / 1e-7f) * WSC;
    if (am == 0 || !(sq > 0.f)) w = 0.f;
    return w;
}

// ============================================================
// Stage 1 (k_prep): ALL 8192 blocks build the adjacency bitmask with
// coalesced BATCHED loads (MLP=8) then ballots (permuted layout:
// word = (j/128)*4 + j%4, bit = (j%128)/4). Blocks < 512 additionally
// compute u = feat@W and x = expmap0(u).
// ============================================================
__global__ __launch_bounds__(256) void k_prep(const float* __restrict__ feat,
                                              const float* __restrict__ W,
                                              const int* __restrict__ adj) {
    __shared__ float fs[16][DD];   // 16 KB
    __shared__ float us[16][UU];   // 8 KB
    int tid = threadIdx.x;
    int wid = tid >> 5, lane = tid & 31;

    // ---- adjacency bitmask: warp handles 1024 consecutive ints ----
    {
        size_t warpg = (size_t)blockIdx.x * 8 + wid;
        const uint4* ap = (const uint4*)adj + warpg * 256;
        uint4 v[8];
        #pragma unroll
        for (int i = 0; i < 8; i++) v[i] = ap[i * 32 + lane];   // batched: MLP=8
        uint32_t myword = 0;
        #pragma unroll
        for (int i = 0; i < 8; i++) {
            uint32_t b0 = __ballot_sync(0xffffffffu, v[i].x != 0);
            uint32_t b1 = __ballot_sync(0xffffffffu, v[i].y != 0);
            uint32_t b2 = __ballot_sync(0xffffffffu, v[i].z != 0);
            uint32_t b3 = __ballot_sync(0xffffffffu, v[i].w != 0);
            if ((lane >> 2) == i) {
                int k = lane & 3;
                myword = (k == 0) ? b0 : (k == 1) ? b1 : (k == 2) ? b2 : b3;
            }
        }
        g_adjb[warpg * 32 + lane] = myword;
    }

    if (blockIdx.x >= NN / 16) return;
    int r0 = blockIdx.x * 16;

    // ---- u = feat @ W (16 rows) ----
    for (int idx = tid; idx < 16 * DD; idx += 256)
        fs[idx >> 8][idx & 255] = feat[(size_t)(r0 + (idx >> 8)) * DD + (idx & 255)];
    __syncthreads();

    int col = tid & 127, rg = tid >> 7;
    float acc[8] = {0.f,0.f,0.f,0.f,0.f,0.f,0.f,0.f};
    for (int d = 0; d < DD; d++) {
        float kv = W[d * UU + col];
        #pragma unroll
        for (int r = 0; r < 8; r++)
            acc[r] = fmaf(fs[rg * 8 + r][d], kv, acc[r]);
    }
    #pragma unroll
    for (int r = 0; r < 8; r++)
        us[rg * 8 + r][col] = acc[r];
    __syncthreads();

    // ---- expmap0 per row (row = tid>>4, cols seg*8..seg*8+7) ----
    int row = tid >> 4, seg = tid & 15;
    float v[8], p2 = 0.f;
    #pragma unroll
    for (int q = 0; q < 8; q++) {
        v[q] = us[row][seg * 8 + q];
        p2 = fmaf(v[q], v[q], p2);
    }
    #pragma unroll
    for (int o = 8; o > 0; o >>= 1)
        p2 += __shfl_xor_sync(0xffffffffu, p2, o);
    float n  = fmaxf(sqrtf(p2), 1e-15f);
    float tn = tanhf(n);
    float fac = tn / n;

    __half2 oh[4], ol[4];
    #pragma unroll
    for (int q = 0; q < 4; q++) {
        float x0 = fac * v[2 * q], x1 = fac * v[2 * q + 1];
        __half h0 = __float2half_rn(x0), h1 = __float2half_rn(x1);
        oh[q] = __halves2half2(h0, h1);
        ol[q] = __halves2half2(__float2half_rn(x0 - __half2float(h0)),
                               __float2half_rn(x1 - __half2float(h1)));
    }
    *(uint4*)&g_xh[(size_t)(r0 + row) * UU + seg * 8] = *(uint4*)oh;
    *(uint4*)&g_xl[(size_t)(r0 + row) * UU + seg * 8] = *(uint4*)ol;
    if (seg == 0) g_x2[r0 + row] = tn * tn;
}

// ============================================================
// Stage 2 (k_fused): scores + aggregation, fp16 HMMA.
// grid 256 = 128 ib x 2 jh; 256 threads; warps 4(m16) x 2(j32).
// GEMM1: 2 products (xh_i.xh_j + xl_i.xh_j) -- Al RESIDENT, no Bl tile;
// GEMM2: 1 product (wh.xh) -- wl residual dropped (random-sign, ~1.4e-4 RMS).
// Per chunk only ONE Bh tile streams through smem.
// smem: [Ah][Al][Bh0][Bh1] + RS  (68.5 KB -> 2 CTA/SM)
// ============================================================
#define SKA 136
#define AT64 (64 * SKA * 2)            /* 17408 B per 64-row fp16 tile */
#define OS_OFF (2 * AT64)              /* O-reduce staging reuses Bh tiles */
#define RS_OFF (4 * AT64)
#define G1_SMEM (4 * AT64 + 512)       /* 70144 B */

__device__ __forceinline__ void cp_tile64(char* dst, const __half* src,
                                          int r0, int tid) {
    #pragma unroll
    for (int it = 0; it < 4; it++) {
        int idx = it * 256 + tid;
        int row = idx >> 4, q = idx & 15;
        cp16(smem_to_u32(dst + (row * SKA + q * 8) * 2),
             (const void*)(src + (size_t)(r0 + row) * UU + q * 8));
    }
}

__global__ __launch_bounds__(256, 2) void k_fused() {
    extern __shared__ char smc[];
    uint32_t sb = smem_to_u32(smc);
    int tid = threadIdx.x, wid = tid >> 5, lane = tid & 31;
    int ib = blockIdx.x >> 1, jh = blockIdx.x & 1;
    int i0 = ib * 64, jbase = jh * 4096;

    int wm = (wid & 3) * 16, wn = (wid >> 2) * 32;
    int g = lane >> 2, tq = lane & 3;
    int aRow = (lane & 7) + ((lane >> 3) & 1) * 8;
    int aCol = (lane >> 4) * 8;
    int bRow = (lane & 7) + (lane >> 4) * 8;
    int bCol = ((lane >> 3) & 1) * 8;
    int tm = lane >> 3, tr = lane & 7;          // trans-ldsm lane mapping
    int k0w = (tq & 1) * 2;                      // adj word pair select

    // prologue: Ah + Al resident + Bh(c=0)
    cp_tile64(smc + 0 * AT64, g_xh, i0, tid);
    cp_tile64(smc + 1 * AT64, g_xl, i0, tid);
    cp_tile64(smc + 2 * AT64, g_xh, jbase, tid);
    CP_COMMIT();

    float x2i[2];
    x2i[0] = g_x2[i0 + wm + g];
    x2i[1] = g_x2[i0 + wm + g + 8];

    float rsum[2] = {0.f, 0.f};
    float o[16][4];
    #pragma unroll
    for (int nb = 0; nb < 16; nb++)
        #pragma unroll
        for (int q = 0; q < 4; q++) o[nb][q] = 0.f;

    CP_WAIT0();
    __syncthreads();

    for (int c = 0; c < 64; c++) {
        int s = c & 1;
        if (c < 63) {   // prefetch next 64-row Bh tile into the other stage
            int jn = jbase + (c + 1) * 64;
            cp_tile64(smc + (uint32_t)(2 + (s ^ 1)) * AT64, g_xh, jn, tid);
            CP_COMMIT();
        }
        uint32_t Bh = sb + (uint32_t)(2 + s) * AT64;

        // ---- GEMM1: xy scores, 2 products (hh + lh), A-lo resident ----
        float acc[4][4];
        #pragma unroll
        for (int nb = 0; nb < 4; nb++)
            #pragma unroll
            for (int q = 0; q < 4; q++) acc[nb][q] = 0.f;

        uint32_t Ah = sb, Al = sb + AT64;
        #pragma unroll
        for (int ksv = 0; ksv < 8; ksv++) {
            int k0 = ksv * 16;
            uint32_t ah[4], al[4], bh[2][4];
            ldsm4(ah[0], ah[1], ah[2], ah[3],
                  Ah + (uint32_t)((wm + aRow) * SKA + k0 + aCol) * 2);
            ldsm4(al[0], al[1], al[2], al[3],
                  Al + (uint32_t)((wm + aRow) * SKA + k0 + aCol) * 2);
            #pragma unroll
            for (int nb = 0; nb < 2; nb++)
                ldsm4(bh[nb][0], bh[nb][1], bh[nb][2], bh[nb][3],
                      Bh + (uint32_t)((wn + nb * 16 + bRow) * SKA + k0 + bCol) * 2);
            #pragma unroll
            for (int nb = 0; nb < 2; nb++) {
                mma_f16(acc[2 * nb],     ah, bh[nb][0], bh[nb][1]);
                mma_f16(acc[2 * nb + 1], ah, bh[nb][2], bh[nb][3]);
                mma_f16(acc[2 * nb],     al, bh[nb][0], bh[nb][1]);
                mma_f16(acc[2 * nb + 1], al, bh[nb][2], bh[nb][3]);
            }
        }

        // ---- score epilogue: scaled w -> fp16 A fragments (hi only) ----
        int jc = jbase + c * 64;
        int blk = (jc + wn) >> 7;
        int tb = ((c & 1) << 4) + (wn >> 2) + (tq >> 1);
        float2 x2jv[4];
        #pragma unroll
        for (int nbi = 0; nbi < 4; nbi++)
            x2jv[nbi] = *(const float2*)&g_x2[jc + wn + nbi * 8 + 2 * tq];

        uint32_t wh[2][4];
        #pragma unroll
        for (int rh = 0; rh < 2; rh++) {
            int ig = i0 + wm + g + rh * 8;
            uint2 mw = *(const uint2*)&g_adjb[(size_t)ig * 256 + blk * 4 + k0w];
            float x2iv = x2i[rh];
            float rs = 0.f;
            #pragma unroll
            for (int nbi = 0; nbi < 4; nbi++) {
                int tt = tb + 2 * nbi;
                int a0 = (mw.x >> tt) & 1;
                int a1 = (mw.y >> tt) & 1;
                float w0 = score_w(acc[nbi][rh * 2 + 0], x2iv, x2jv[nbi].x, a0);
                float w1 = score_w(acc[nbi][rh * 2 + 1], x2iv, x2jv[nbi].y, a1);
                rs += w0 + w1;
                int ks = nbi >> 1, ai = (nbi & 1) * 2 + rh;
                wh[ks][ai] = cvt_f16x2(w1, w0);
            }
            rsum[rh] += rs;
        }

        // ---- GEMM2: O += W * Xj  (Bh trans-ldsm; wh product only) ----
        #pragma unroll
        for (int ks = 0; ks < 2; ks++) {
            #pragma unroll
            for (int np = 0; np < 8; np++) {
                uint32_t off = (uint32_t)((wn + ks * 16 + (tm & 1) * 8 + tr) * SKA
                                          + np * 16 + (tm >> 1) * 8) * 2;
                uint32_t bt0, bt1, bt2, bt3;
                ldsm4t(bt0, bt1, bt2, bt3, Bh + off);
                mma_f16(o[np * 2],     wh[ks], bt0, bt1);
                mma_f16(o[np * 2 + 1], wh[ks], bt2, bt3);
            }
        }

        if (c < 63) CP_WAIT0();
        __syncthreads();
    }

    // ---- rsum combine + O cross-warp reduction ----
    #pragma unroll
    for (int r = 0; r < 2; r++) {
        rsum[r] += __shfl_xor_sync(0xffffffffu, rsum[r], 1);
        rsum[r] += __shfl_xor_sync(0xffffffffu, rsum[r], 2);
    }
    float* RS = (float*)(smc + RS_OFF);    // [8 warps][16 rows]
    if (tq == 0) {
        RS[wid * 16 + g]     = rsum[0];
        RS[wid * 16 + 8 + g] = rsum[1];
    }
    float* OS = (float*)(smc + OS_OFF);    // 32KB staging (reuses Bh tiles)
    if (wid >= 4) {
        #pragma unroll
        for (int nb = 0; nb < 16; nb++)
            #pragma unroll
            for (int q = 0; q < 4; q++)
                OS[(wid - 4) * 2048 + (nb * 4 + q) * 32 + lane] = o[nb][q];
    }
    __syncthreads();

    if (tid < 64) {
        int mt = tid >> 4, idx = tid & 15;
        float v = RS[mt * 16 + idx] + RS[(mt + 4) * 16 + idx];
        g_rsump[(i0 + mt * 16 + idx) * 2 + jh] = v;
    }
    if (wid < 4) {
        #pragma unroll
        for (int nb = 0; nb < 16; nb++) {
            float p0 = OS[wid * 2048 + (nb * 4 + 0) * 32 + lane];
            float p1 = OS[wid * 2048 + (nb * 4 + 1) * 32 + lane];
            float p2 = OS[wid * 2048 + (nb * 4 + 2) * 32 + lane];
            float p3 = OS[wid * 2048 + (nb * 4 + 3) * 32 + lane];
            int irow = i0 + wm + g;
            int dcol = nb * 8 + 2 * tq;
            *(float2*)&g_mx2[((size_t)jh * NN + irow) * UU + dcol] =
                make_float2(o[nb][0] + p0, o[nb][1] + p1);
            *(float2*)&g_mx2[((size_t)jh * NN + irow + 8) * UU + dcol] =
                make_float2(o[nb][2] + p2, o[nb][3] + p3);
        }
    }
}

// ============================================================
// Stage 3: combine halves, normalize, hyperbolic rescale + mobius bias
// (w-scale 2^-10 cancels in O/rsum)
// ============================================================
__global__ __launch_bounds__(128) void k_epilogue(const float* __restrict__ bias,
                                                  float* __restrict__ out) {
    __shared__ float sm[4];
    int row = blockIdx.x, t = threadIdx.x;

    float rp = (t < 2) ? g_rsump[row * 2 + t] : 0.f;
    float rs = blockReduce128(rp, sm);

    float m = __fdividef(g_mx2[(size_t)row * UU + t] +
                         g_mx2[(size_t)(NN + row) * UU + t], rs);
    float mn2 = blockReduce128(m * m, sm);
    float x2i = g_x2[row];
    float x_n  = fmaxf(sqrtf(x2i), 1e-15f);
    float mx_n = fmaxf(sqrtf(mn2), 1e-15f);
    float xa   = fminf(x_n, 1.f - 1e-7f);
    float art  = 0.5f * (log1pf(xa) - log1pf(-xa));
    float alpha = __fdividef(tanhf(__fdividef(mx_n, x_n) * art), mx_n);
    float ov = alpha * m;

    float bv  = bias[t];
    float bn2 = blockReduce128(bv * bv, sm);
    float bn  = fmaxf(sqrtf(bn2), 1e-15f);
    float bvx = __fdividef(tanhf(bn), bn) * bv;

    float y2  = blockReduce128(bvx * bvx, sm);
    float xy  = blockReduce128(ov * bvx, sm);
    float x2o = blockReduce128(ov * ov, sm);
    float cx  = 1.f + 2.f * xy + y2;
    float cy  = 1.f - x2o;
    float den = fmaxf(fmaf(x2o, y2, 1.f + 2.f * xy), 1e-15f);
    out[(size_t)row * UU + t] = __fdividef(cx * ov + cy * bvx, den);
}

// ============================================================
extern "C" void kernel_launch(void* const* d_in, const int* in_sizes, int n_in,
                              void* d_out, int out_size) {
    const float* feat = (const float*)d_in[0];
    const int*   adj  = (const int*)  d_in[1];
    const float* W    = (const float*)d_in[2];
    const float* bias = (const float*)d_in[3];
    float* out = (float*)d_out;

    cudaFuncSetAttribute(k_fused, cudaFuncAttributeMaxDynamicSharedMemorySize, G1_SMEM);

    k_prep    <<<NN * NN / 32 / 256, 256>>>(feat, W, adj);
    k_fused   <<<256, 256, G1_SMEM>>>();
    k_epilogue<<<NN, 128>>>(bias, out);
}